// round 10
// baseline (speedup 1.0000x reference)
#include <cuda_runtime.h>
#include <cuda_fp16.h>
#include <cstdint>

// ---------------------------------------------------------------------------
// SparseGaussianHead: two sparse-conv layers (27-offset gather-GEMM) + GELU
//   L1: [400k x 64] -> [400k x 38]   (N padded to 40)
//   L2: [400k x 38] -> [400k x 38]   (K padded to 48, N padded to 40)
// fp16 m16n8k16 MMA, fp32 accumulate.
// R7: R6 structure (256 rows/CTA, B reuse x4, dirty-tracked A rows) +
//     2-stage software pipeline: gather/W of offset k+1 overlaps MMA of k.
// ---------------------------------------------------------------------------

#define NPTS 400000
#define NOFF 27

__device__ __half g_feat[NPTS * 64];          // features, fp16
__device__ __half g_h[NPTS * 48];             // gelu out, cols 38..47 = 0
__device__ __half g_W1t[NOFF * 40 * 72];      // W1^T [k][n][c], stride 72 halves
__device__ __half g_W2t[NOFF * 40 * 56];      // W2^T [k][n][c], stride 56 halves

__device__ __forceinline__ float gelu_exact(float x) {
    return 0.5f * x * (1.0f + erff(x * 0.7071067811865476f));
}

// ------------------------------ prep kernels ------------------------------

__global__ void prep_feat(const float* __restrict__ F) {
    int e = blockIdx.x * 256 + threadIdx.x;   // NPTS*64 exact multiple of 256
    g_feat[e] = __float2half_rn(F[e]);
}

__global__ void prep_w1(const float* __restrict__ W1) {
    int e = blockIdx.x * 256 + threadIdx.x;
    if (e >= NOFF * 40 * 64) return;
    int c = e & 63;               // input channel (K dim)
    int n = (e >> 6) % 40;        // output channel
    int k = e / (64 * 40);
    float v = (n < 38) ? W1[(k * 64 + c) * 38 + n] : 0.0f;
    g_W1t[k * (40 * 72) + n * 72 + c] = __float2half_rn(v);
}

__global__ void prep_w2(const float* __restrict__ W2) {
    int e = blockIdx.x * 256 + threadIdx.x;
    if (e >= NOFF * 40 * 48) return;
    int c = e % 48;
    int rest = e / 48;
    int n = rest % 40;
    int k = rest / 40;
    float v = (n < 38 && c < 38) ? W2[(k * 38 + c) * 38 + n] : 0.0f;
    g_W2t[k * (40 * 56) + n * 56 + c] = __float2half_rn(v);
}

// ------------------------------ conv kernel -------------------------------
// 128 threads = 4 warps; CTA tile 256 rows x 40 cols; warp w owns rows
// 64w..64w+63 (four m16 tiles, B fragments reused 4x). Thread tid gathers
// local rows tid and tid+128. Double-buffered A and W: stage k+1 loads
// overlap stage k MMAs.
// MODE 0: in g_feat, out g_h (exact GELU, fp16, cols 40..47 zeroed)
// MODE 1: in g_h,    out d_out (first 38 cols, fp32)

template <int KD, int MODE>
__global__ __launch_bounds__(128) void conv_k(const int* __restrict__ nbr,
                                              float* __restrict__ dout) {
    constexpr int AS   = (KD == 64) ? 72 : 56;  // halves per A/W row (16B mult)
    constexpr int CHK  = KD / 8;                // 16B chunks per A row (8 / 6)
    constexpr int KK   = KD / 16;               // K-steps (4 / 3)
    constexpr int WCHK = 5 * AS;                // 16B chunks in W tile

    __shared__ __half As[2][256 * AS];
    __shared__ __half Ws[2][40 * AS];

    const __half* __restrict__ feat = (MODE == 0) ? g_feat : g_h;
    const __half* __restrict__ Wg   = (MODE == 0) ? g_W1t  : g_W2t;

    const int tid  = threadIdx.x;
    const int warp = tid >> 5;
    const int lane = tid & 31;
    const int g    = lane >> 2;   // 0..7
    const int t    = lane & 3;    // 0..3
    const int base = blockIdx.x * 256;

    const unsigned as_base = (unsigned)__cvta_generic_to_shared(As);
    const unsigned ws_base = (unsigned)__cvta_generic_to_shared(Ws);
    constexpr unsigned ABUF = 256 * AS * 2;     // bytes per A buffer
    constexpr unsigned WBUF = 40 * AS * 2;      // bytes per W buffer

    float acc[4][5][4];
#pragma unroll
    for (int tt = 0; tt < 4; tt++)
#pragma unroll
        for (int j = 0; j < 5; j++)
#pragma unroll
            for (int q = 0; q < 4; q++) acc[tt][j][q] = 0.0f;

    // zero owned rows in BOTH buffers once; rewrite only on state change
    {
        const float4 z = make_float4(0.f, 0.f, 0.f, 0.f);
#pragma unroll
        for (int bb = 0; bb < 2; bb++)
#pragma unroll
            for (int m = 0; m < CHK; m++) {
                *(float4*)&As[bb][(size_t)tid * AS + 8 * m]         = z;
                *(float4*)&As[bb][(size_t)(tid + 128) * AS + 8 * m] = z;
            }
    }
    bool dirty[2][2] = {{false, false}, {false, false}};

    // gather one A row of offset k into buffer b (dirty-tracked)
    auto do_gather = [&](int k, int lrow, int b, bool& dr) {
        const int grow = base + lrow;
        int idx = NPTS;
        if (grow < NPTS) idx = __ldg(&nbr[k * NPTS + grow]);
        const bool valid = (unsigned)idx < (unsigned)NPTS;
        if (valid) {
            const char* src = (const char*)(feat + (size_t)idx * KD);
            const unsigned dst = as_base + (unsigned)b * ABUF
                               + (unsigned)(lrow * AS) * 2u;
#pragma unroll
            for (int m = 0; m < CHK; m++)
                asm volatile("cp.async.ca.shared.global [%0], [%1], 16;"
                             :: "r"(dst + (unsigned)(16 * m)),
                                "l"(src + 16 * m));
        } else if (dr) {
            const float4 z = make_float4(0.f, 0.f, 0.f, 0.f);
#pragma unroll
            for (int m = 0; m < CHK; m++)
                *(float4*)&As[b][(size_t)lrow * AS + 8 * m] = z;
        }
        dr = valid;
    };
    auto do_w = [&](int k, int b) {
        const char* wsrc = (const char*)(Wg + (size_t)k * 40 * AS);
        const unsigned wb = ws_base + (unsigned)b * WBUF;
#pragma unroll
        for (int e = tid; e < WCHK; e += 128)
            asm volatile("cp.async.ca.shared.global [%0], [%1], 16;"
                         :: "r"(wb + (unsigned)(16 * e)), "l"(wsrc + 16 * e));
    };

    // prologue: stage 0 into buffer 0
    do_gather(0, tid, 0, dirty[0][0]);
    do_gather(0, tid + 128, 0, dirty[0][1]);
    do_w(0, 0);
    asm volatile("cp.async.commit_group;" ::: "memory");

    for (int k = 0; k < NOFF; k++) {
        const int b = k & 1;

        // issue stage k+1 into the other buffer (overlaps this stage's MMA)
        if (k + 1 < NOFF) {
            const int nb = b ^ 1;
            do_gather(k + 1, tid, nb, dirty[nb][0]);
            do_gather(k + 1, tid + 128, nb, dirty[nb][1]);
            do_w(k + 1, nb);
            asm volatile("cp.async.commit_group;" ::: "memory");
            asm volatile("cp.async.wait_group 1;" ::: "memory");  // stage k done
        } else {
            asm volatile("cp.async.wait_group 0;" ::: "memory");
        }
        __syncthreads();   // stage-k data visible to all warps

        // --- MMA: [256 x KD] @ [KD x 40]; warp w rows 64w..64w+63 ---
        const __half* __restrict__ A = As[b];
        const __half* __restrict__ W = Ws[b];
#pragma unroll
        for (int kk = 0; kk < KK; ++kk) {
            const int kc = kk * 16 + 2 * t;
            unsigned a[4][4];
#pragma unroll
            for (int tt = 0; tt < 4; tt++) {
                const int r = warp * 64 + tt * 16 + g;
                a[tt][0] = *(const unsigned*)&A[r * AS + kc];
                a[tt][1] = *(const unsigned*)&A[(r + 8) * AS + kc];
                a[tt][2] = *(const unsigned*)&A[r * AS + kc + 8];
                a[tt][3] = *(const unsigned*)&A[(r + 8) * AS + kc + 8];
            }
#pragma unroll
            for (int j = 0; j < 5; j++) {
                const unsigned b0 = *(const unsigned*)&W[(j * 8 + g) * AS + kc];
                const unsigned b1 = *(const unsigned*)&W[(j * 8 + g) * AS + kc + 8];
#pragma unroll
                for (int tt = 0; tt < 4; tt++) {
                    asm volatile(
                        "mma.sync.aligned.m16n8k16.row.col.f32.f16.f16.f32 "
                        "{%0,%1,%2,%3}, {%4,%5,%6,%7}, {%8,%9}, {%0,%1,%2,%3};\n"
                        : "+f"(acc[tt][j][0]), "+f"(acc[tt][j][1]),
                          "+f"(acc[tt][j][2]), "+f"(acc[tt][j][3])
                        : "r"(a[tt][0]), "r"(a[tt][1]), "r"(a[tt][2]),
                          "r"(a[tt][3]), "r"(b0), "r"(b1));
                }
            }
        }
        __syncthreads();   // MMA(k) done before stage k+2 overwrites buffer b
    }

    // --- epilogue (guard ragged last CTA) ---
#pragma unroll
    for (int tt = 0; tt < 4; tt++) {
        const int r0 = base + warp * 64 + tt * 16 + g;
#pragma unroll
        for (int j = 0; j < 5; j++) {
            const int c0 = j * 8 + 2 * t;
            if (MODE == 0) {
                if (r0 < NPTS) {
                    __half2* h0 = (__half2*)&g_h[(size_t)r0 * 48 + c0];
                    *h0 = __floats2half2_rn(gelu_exact(acc[tt][j][0]),
                                            gelu_exact(acc[tt][j][1]));
                }
                if (r0 + 8 < NPTS) {
                    __half2* h1 = (__half2*)&g_h[(size_t)(r0 + 8) * 48 + c0];
                    *h1 = __floats2half2_rn(gelu_exact(acc[tt][j][2]),
                                            gelu_exact(acc[tt][j][3]));
                }
            } else {
                if (r0 < NPTS) {
                    if (c0 < 38)     dout[(size_t)r0 * 38 + c0]     = acc[tt][j][0];
                    if (c0 + 1 < 38) dout[(size_t)r0 * 38 + c0 + 1] = acc[tt][j][1];
                }
                if (r0 + 8 < NPTS) {
                    if (c0 < 38)     dout[(size_t)(r0 + 8) * 38 + c0]     = acc[tt][j][2];
                    if (c0 + 1 < 38) dout[(size_t)(r0 + 8) * 38 + c0 + 1] = acc[tt][j][3];
                }
            }
        }
        if (MODE == 0 && t == 0) {   // zero pad cols 40..47
            const float4 z = make_float4(0.f, 0.f, 0.f, 0.f);
            if (r0 < NPTS)     *(float4*)&g_h[(size_t)r0 * 48 + 40]       = z;
            if (r0 + 8 < NPTS) *(float4*)&g_h[(size_t)(r0 + 8) * 48 + 40] = z;
        }
    }
}

// ------------------------------ launch ------------------------------------

extern "C" void kernel_launch(void* const* d_in, const int* in_sizes, int n_in,
                              void* d_out, int out_size) {
    const float* F   = (const float*)d_in[0];   // [400000, 64]
    const int*   nbr = (const int*)d_in[1];     // [27, 400000]
    const float* W1  = (const float*)d_in[2];   // [27, 64, 38]
    const float* W2  = (const float*)d_in[3];   // [27, 38, 38]
    float* out = (float*)d_out;                 // [400000, 38]

    prep_feat<<<(NPTS * 64) / 256, 256>>>(F);
    prep_w1<<<(NOFF * 40 * 64 + 255) / 256, 256>>>(W1);
    prep_w2<<<(NOFF * 40 * 48 + 255) / 256, 256>>>(W2);

    const int grid = (NPTS + 255) / 256;        // 1563 (last CTA ragged)
    conv_k<64, 0><<<grid, 128>>>(nbr, nullptr); // L1 + GELU -> g_h
    conv_k<48, 1><<<grid, 128>>>(nbr, out);     // L2 -> d_out
}

// round 11
// speedup vs baseline: 1.8288x; 1.8288x over previous
#include <cuda_runtime.h>
#include <cuda_fp16.h>
#include <cstdint>

// ---------------------------------------------------------------------------
// SparseGaussianHead: two sparse-conv layers (27-offset gather-GEMM) + GELU
//   L1: [400k x 64] -> [400k x 38]   (N padded to 40)
//   L2: [400k x 38] -> [400k x 38]   (K padded to 48, N padded to 40)
// fp16 m16n8k16 MMA, fp32 accumulate.
// R8: NO shared memory, NO barriers. A fragments gathered straight to
//     registers via __ldg with a zero pad-row at index NPTS (branch-free
//     invalid handling); B fragments pre-packed lane-major (1 coalesced
//     L1-hot LDG per fragment register).
// ---------------------------------------------------------------------------

#define NPTS 400000
#define NOFF 27

__device__ __half g_feat[(NPTS + 1) * 64];    // features fp16 + zero pad row
__device__ __half g_h[(NPTS + 1) * 48];       // gelu out (cols 38..47 = 0) + pad row
// packed B fragments: [k][j][kk][q][lane] as half2-in-uint
__device__ unsigned g_W1f[NOFF * 5 * 4 * 2 * 32];
__device__ unsigned g_W2f[NOFF * 5 * 3 * 2 * 32];

__device__ __forceinline__ float gelu_exact(float x) {
    return 0.5f * x * (1.0f + erff(x * 0.7071067811865476f));
}

// ------------------------------ prep kernels ------------------------------

__global__ void prep_feat(const float* __restrict__ F) {
    int e = blockIdx.x * 256 + threadIdx.x;
    if (e < NPTS * 64)
        g_feat[e] = __float2half_rn(F[e]);
    else if (e < (NPTS + 1) * 64)
        g_feat[e] = __float2half_rn(0.0f);          // pad row
    if (e < 48)
        g_h[(size_t)NPTS * 48 + e] = __float2half_rn(0.0f);  // pad row of g_h
}

// pack W1 [27][64][38] -> fragments: e = (((k*5+j)*4+kk)*2+q)*32 + lane
__global__ void prep_w1f(const float* __restrict__ W1) {
    int e = blockIdx.x * 256 + threadIdx.x;
    if (e >= NOFF * 5 * 4 * 2 * 32) return;
    int lane = e & 31;
    int r = e >> 5;
    int q = r & 1;  r >>= 1;
    int kk = r % 4; r /= 4;
    int j = r % 5;  r /= 5;
    int k = r;
    int g = lane >> 2, t = lane & 3;
    int n = j * 8 + g;
    int c = 16 * kk + 2 * t + 8 * q;      // 0..63
    float v0 = (n < 38) ? W1[(k * 64 + c) * 38 + n] : 0.0f;
    float v1 = (n < 38) ? W1[(k * 64 + c + 1) * 38 + n] : 0.0f;
    __half2 h = __floats2half2_rn(v0, v1);
    g_W1f[e] = *(unsigned*)&h;
}

// pack W2 [27][38][38] -> fragments (K padded to 48): kk in 0..2
__global__ void prep_w2f(const float* __restrict__ W2) {
    int e = blockIdx.x * 256 + threadIdx.x;
    if (e >= NOFF * 5 * 3 * 2 * 32) return;
    int lane = e & 31;
    int r = e >> 5;
    int q = r & 1;  r >>= 1;
    int kk = r % 3; r /= 3;
    int j = r % 5;  r /= 5;
    int k = r;
    int g = lane >> 2, t = lane & 3;
    int n = j * 8 + g;
    int c = 16 * kk + 2 * t + 8 * q;      // 0..47
    float v0 = (n < 38 && c < 38)     ? W2[(k * 38 + c) * 38 + n]     : 0.0f;
    float v1 = (n < 38 && c + 1 < 38) ? W2[(k * 38 + c + 1) * 38 + n] : 0.0f;
    __half2 h = __floats2half2_rn(v0, v1);
    g_W2f[e] = *(unsigned*)&h;
}

// ------------------------------ conv kernel -------------------------------
// 128 threads = 4 warps; CTA = 128 rows (400000 = 3125 * 128, no raggedness).
// Warp owns 32 rows = two m16 tiles. All operands __ldg'd directly into
// fragment registers; invalid neighbors read the zero pad row (idx == NPTS).
// MODE 0: in g_feat (KD=64), out g_h (exact GELU, fp16, cols 40..47 zeroed)
// MODE 1: in g_h    (KD=48), out d_out (first 38 cols, fp32)

template <int KD, int MODE>
__global__ __launch_bounds__(128) void conv_r(const int* __restrict__ nbr,
                                              float* __restrict__ dout) {
    constexpr int KK = KD / 16;           // 4 / 3
    const __half* __restrict__ feat = (MODE == 0) ? g_feat : g_h;
    const unsigned* __restrict__ Wf = (MODE == 0) ? g_W1f  : g_W2f;

    const int tid  = threadIdx.x;
    const int warp = tid >> 5;
    const int lane = tid & 31;
    const int g    = lane >> 2;   // 0..7
    const int t    = lane & 3;    // 0..3
    const int base = blockIdx.x * 128 + warp * 32;

    float acc[2][5][4];
#pragma unroll
    for (int tt = 0; tt < 2; tt++)
#pragma unroll
        for (int j = 0; j < 5; j++)
#pragma unroll
            for (int q = 0; q < 4; q++) acc[tt][j][q] = 0.0f;

    for (int k = 0; k < NOFF; k++) {
        const int* nk = nbr + k * NPTS + base;
        // fragment row indices (pad row NPTS when invalid -> zeros, no branch)
        const int i00 = __ldg(nk + g);
        const int i01 = __ldg(nk + g + 8);
        const int i10 = __ldg(nk + g + 16);
        const int i11 = __ldg(nk + g + 24);
        const unsigned* r00 = (const unsigned*)(feat + (size_t)i00 * KD);
        const unsigned* r01 = (const unsigned*)(feat + (size_t)i01 * KD);
        const unsigned* r10 = (const unsigned*)(feat + (size_t)i10 * KD);
        const unsigned* r11 = (const unsigned*)(feat + (size_t)i11 * KD);
        const unsigned* wk = Wf + k * (5 * KK * 2 * 32);

#pragma unroll
        for (int kk = 0; kk < KK; ++kk) {
            const int c0 = (kk * 16 + 2 * t) >> 1;     // uint offset
            const int c1 = c0 + 4;                     // +8 halves
            unsigned a[2][4];
            a[0][0] = __ldg(r00 + c0);
            a[0][1] = __ldg(r01 + c0);
            a[0][2] = __ldg(r00 + c1);
            a[0][3] = __ldg(r01 + c1);
            a[1][0] = __ldg(r10 + c0);
            a[1][1] = __ldg(r11 + c0);
            a[1][2] = __ldg(r10 + c1);
            a[1][3] = __ldg(r11 + c1);
#pragma unroll
            for (int j = 0; j < 5; j++) {
                const unsigned b0 = __ldg(wk + ((j * KK + kk) * 2 + 0) * 32 + lane);
                const unsigned b1 = __ldg(wk + ((j * KK + kk) * 2 + 1) * 32 + lane);
#pragma unroll
                for (int tt = 0; tt < 2; tt++) {
                    asm volatile(
                        "mma.sync.aligned.m16n8k16.row.col.f32.f16.f16.f32 "
                        "{%0,%1,%2,%3}, {%4,%5,%6,%7}, {%8,%9}, {%0,%1,%2,%3};\n"
                        : "+f"(acc[tt][j][0]), "+f"(acc[tt][j][1]),
                          "+f"(acc[tt][j][2]), "+f"(acc[tt][j][3])
                        : "r"(a[tt][0]), "r"(a[tt][1]), "r"(a[tt][2]),
                          "r"(a[tt][3]), "r"(b0), "r"(b1));
                }
            }
        }
    }

    // --- epilogue ---
#pragma unroll
    for (int tt = 0; tt < 2; tt++) {
        const int r0 = base + tt * 16 + g;
#pragma unroll
        for (int j = 0; j < 5; j++) {
            const int c0 = j * 8 + 2 * t;
            if (MODE == 0) {
                __half2* h0 = (__half2*)&g_h[(size_t)r0 * 48 + c0];
                __half2* h1 = (__half2*)&g_h[(size_t)(r0 + 8) * 48 + c0];
                *h0 = __floats2half2_rn(gelu_exact(acc[tt][j][0]),
                                        gelu_exact(acc[tt][j][1]));
                *h1 = __floats2half2_rn(gelu_exact(acc[tt][j][2]),
                                        gelu_exact(acc[tt][j][3]));
            } else {
                if (c0 < 38) {
                    dout[(size_t)r0 * 38 + c0]       = acc[tt][j][0];
                    dout[(size_t)(r0 + 8) * 38 + c0] = acc[tt][j][2];
                }
                if (c0 + 1 < 38) {
                    dout[(size_t)r0 * 38 + c0 + 1]       = acc[tt][j][1];
                    dout[(size_t)(r0 + 8) * 38 + c0 + 1] = acc[tt][j][3];
                }
            }
        }
        if (MODE == 0 && t == 0) {   // zero pad cols 40..47
            const float4 z = make_float4(0.f, 0.f, 0.f, 0.f);
            *(float4*)&g_h[(size_t)r0 * 48 + 40]       = z;
            *(float4*)&g_h[(size_t)(r0 + 8) * 48 + 40] = z;
        }
    }
}

// ------------------------------ launch ------------------------------------

extern "C" void kernel_launch(void* const* d_in, const int* in_sizes, int n_in,
                              void* d_out, int out_size) {
    const float* F   = (const float*)d_in[0];   // [400000, 64]
    const int*   nbr = (const int*)d_in[1];     // [27, 400000]
    const float* W1  = (const float*)d_in[2];   // [27, 64, 38]
    const float* W2  = (const float*)d_in[3];   // [27, 38, 38]
    float* out = (float*)d_out;                 // [400000, 38]

    prep_feat<<<((NPTS + 1) * 64 + 255) / 256, 256>>>(F);
    prep_w1f<<<(NOFF * 5 * 4 * 2 * 32 + 255) / 256, 256>>>(W1);
    prep_w2f<<<(NOFF * 5 * 3 * 2 * 32 + 255) / 256, 256>>>(W2);

    conv_r<64, 0><<<NPTS / 128, 128>>>(nbr, nullptr);   // L1 + GELU -> g_h
    conv_r<48, 1><<<NPTS / 128, 128>>>(nbr, out);       // L2 -> d_out
}

// round 13
// speedup vs baseline: 1.9966x; 1.0918x over previous
#include <cuda_runtime.h>
#include <cuda_fp16.h>
#include <cstdint>

// ---------------------------------------------------------------------------
// SparseGaussianHead: two sparse-conv layers (27-offset gather-GEMM) + GELU
//   L1: [400k x 64] -> [400k x 38]   (N padded to 40)
//   L2: [400k x 38] -> [400k x 38]   (K padded to 48, N padded to 40)
// fp16 m16n8k16 MMA, fp32 accumulate. Zero smem, zero barriers (R8) +
// R9: column-permuted feature storage so every A fragment is one LDG.64,
//     and pre-packed (b0,b1) W fragments so every B fragment is one LDG.64.
//     LDG count per warp-offset: 76 -> 40.
// ---------------------------------------------------------------------------

#define NPTS 400000
#define NOFF 27

__device__ __half g_feat[(NPTS + 1) * 64];    // permuted fp16 features + zero pad row
__device__ __half g_h[(NPTS + 1) * 48];       // permuted gelu out + zero pad row
// packed B fragments: [k][j][kk][lane] as uint2 (b0,b1)
__device__ uint2 g_W1f[NOFF * 5 * 4 * 32];
__device__ uint2 g_W2f[NOFF * 5 * 3 * 32];

__device__ __forceinline__ float gelu_exact(float x) {
    return 0.5f * x * (1.0f + erff(x * 0.7071067811865476f));
}

// per-16-column-chunk permutation: logical col c -> storage position.
// Puts cols (2t, 2t+1, 2t+8, 2t+9) at positions (4t, 4t+1, 4t+2, 4t+3).
__device__ __forceinline__ int perm16(int c) {
    int q = c & ~15, r = c & 15;
    int pos = (r < 8) ? ((r >> 1) * 4 + (r & 1))
                      : (((r - 8) >> 1) * 4 + 2 + (r & 1));
    return q | pos;
}

// ------------------------------ prep kernels ------------------------------

__global__ void prep_feat(const float* __restrict__ F) {
    int e = blockIdx.x * 256 + threadIdx.x;
    if (e < NPTS * 64) {
        int row = e >> 6, c = e & 63;
        g_feat[row * 64 + perm16(c)] = __float2half_rn(F[e]);
    } else if (e < (NPTS + 1) * 64) {
        g_feat[e] = __float2half_rn(0.0f);          // pad row
    }
    if (e < 48)
        g_h[(size_t)NPTS * 48 + e] = __float2half_rn(0.0f);  // pad row of g_h
}

// pack W1 [27][64][38] -> uint2 fragments: e = ((k*5+j)*4+kk)*32 + lane
__global__ void prep_w1f(const float* __restrict__ W1) {
    int e = blockIdx.x * 256 + threadIdx.x;
    if (e >= NOFF * 5 * 4 * 32) return;
    int lane = e & 31;
    int r = e >> 5;
    int kk = r % 4; r /= 4;
    int j = r % 5;  r /= 5;
    int k = r;
    int g = lane >> 2, t = lane & 3;
    int n = j * 8 + g;
    int c = 16 * kk + 2 * t;
    uint2 v;
    float x0 = (n < 38) ? W1[(k * 64 + c) * 38 + n]     : 0.0f;
    float x1 = (n < 38) ? W1[(k * 64 + c + 1) * 38 + n] : 0.0f;
    float y0 = (n < 38) ? W1[(k * 64 + c + 8) * 38 + n] : 0.0f;
    float y1 = (n < 38) ? W1[(k * 64 + c + 9) * 38 + n] : 0.0f;
    __half2 hx = __floats2half2_rn(x0, x1);
    __half2 hy = __floats2half2_rn(y0, y1);
    v.x = *(unsigned*)&hx;
    v.y = *(unsigned*)&hy;
    g_W1f[e] = v;
}

// pack W2 [27][38][38] -> uint2 fragments (K padded to 48): kk in 0..2
__global__ void prep_w2f(const float* __restrict__ W2) {
    int e = blockIdx.x * 256 + threadIdx.x;
    if (e >= NOFF * 5 * 3 * 32) return;
    int lane = e & 31;
    int r = e >> 5;
    int kk = r % 3; r /= 3;
    int j = r % 5;  r /= 5;
    int k = r;
    int g = lane >> 2, t = lane & 3;
    int n = j * 8 + g;
    int c = 16 * kk + 2 * t;
    auto w2 = [&](int cc) -> float {
        return (n < 38 && cc < 38) ? W2[(k * 38 + cc) * 38 + n] : 0.0f;
    };
    uint2 v;
    __half2 hx = __floats2half2_rn(w2(c), w2(c + 1));
    __half2 hy = __floats2half2_rn(w2(c + 8), w2(c + 9));
    v.x = *(unsigned*)&hx;
    v.y = *(unsigned*)&hy;
    g_W2f[e] = v;
}

// ------------------------------ conv kernel -------------------------------
// 128 threads = 4 warps; CTA = 128 rows (400000 = 3125 * 128).
// Warp owns 32 rows = two m16 tiles. All operands LDG.64 straight into
// fragment registers; invalid neighbors read the zero pad row (idx == NPTS).
// MODE 0: in g_feat (KD=64), out g_h (exact GELU, fp16, permuted cols)
// MODE 1: in g_h    (KD=48), out d_out (first 38 cols, fp32)

template <int KD, int MODE>
__global__ __launch_bounds__(128) void conv_r(const int* __restrict__ nbr,
                                              float* __restrict__ dout) {
    constexpr int KK = KD / 16;           // 4 / 3
    const __half* __restrict__ feat = (MODE == 0) ? g_feat : g_h;
    const uint2* __restrict__ Wf    = (MODE == 0) ? g_W1f  : g_W2f;

    const int tid  = threadIdx.x;
    const int warp = tid >> 5;
    const int lane = tid & 31;
    const int g    = lane >> 2;   // 0..7
    const int t    = lane & 3;    // 0..3
    const int base = blockIdx.x * 128 + warp * 32;

    float acc[2][5][4];
#pragma unroll
    for (int tt = 0; tt < 2; tt++)
#pragma unroll
        for (int j = 0; j < 5; j++)
#pragma unroll
            for (int q = 0; q < 4; q++) acc[tt][j][q] = 0.0f;

    for (int k = 0; k < NOFF; k++) {
        const int* nk = nbr + k * NPTS + base;
        // fragment row indices (pad row NPTS when invalid -> zeros, no branch)
        const int i00 = __ldg(nk + g);
        const int i01 = __ldg(nk + g + 8);
        const int i10 = __ldg(nk + g + 16);
        const int i11 = __ldg(nk + g + 24);
        const uint2* r00 = (const uint2*)(feat + (size_t)i00 * KD);
        const uint2* r01 = (const uint2*)(feat + (size_t)i01 * KD);
        const uint2* r10 = (const uint2*)(feat + (size_t)i10 * KD);
        const uint2* r11 = (const uint2*)(feat + (size_t)i11 * KD);
        const uint2* wk = Wf + k * (5 * KK * 32);

#pragma unroll
        for (int kk = 0; kk < KK; ++kk) {
            const int co = kk * 4 + t;    // uint2 offset in permuted row
            const uint2 v00 = __ldg(r00 + co);
            const uint2 v01 = __ldg(r01 + co);
            const uint2 v10 = __ldg(r10 + co);
            const uint2 v11 = __ldg(r11 + co);
#pragma unroll
            for (int j = 0; j < 5; j++) {
                const uint2 bv = __ldg(wk + (j * KK + kk) * 32 + lane);
                asm volatile(
                    "mma.sync.aligned.m16n8k16.row.col.f32.f16.f16.f32 "
                    "{%0,%1,%2,%3}, {%4,%5,%6,%7}, {%8,%9}, {%0,%1,%2,%3};\n"
                    : "+f"(acc[0][j][0]), "+f"(acc[0][j][1]),
                      "+f"(acc[0][j][2]), "+f"(acc[0][j][3])
                    : "r"(v00.x), "r"(v01.x), "r"(v00.y), "r"(v01.y),
                      "r"(bv.x), "r"(bv.y));
                asm volatile(
                    "mma.sync.aligned.m16n8k16.row.col.f32.f16.f16.f32 "
                    "{%0,%1,%2,%3}, {%4,%5,%6,%7}, {%8,%9}, {%0,%1,%2,%3};\n"
                    : "+f"(acc[1][j][0]), "+f"(acc[1][j][1]),
                      "+f"(acc[1][j][2]), "+f"(acc[1][j][3])
                    : "r"(v10.x), "r"(v11.x), "r"(v10.y), "r"(v11.y),
                      "r"(bv.x), "r"(bv.y));
            }
        }
    }

    // --- epilogue ---
#pragma unroll
    for (int tt = 0; tt < 2; tt++) {
        const int r0 = base + tt * 16 + g;
#pragma unroll
        for (int j = 0; j < 5; j++) {
            const int c0 = j * 8 + 2 * t;
            if (MODE == 0) {
                const int pc = perm16(c0);   // pair (c0, c0+1) stays adjacent
                __half2* h0 = (__half2*)&g_h[(size_t)r0 * 48 + pc];
                __half2* h1 = (__half2*)&g_h[(size_t)(r0 + 8) * 48 + pc];
                *h0 = __floats2half2_rn(gelu_exact(acc[tt][j][0]),
                                        gelu_exact(acc[tt][j][1]));
                *h1 = __floats2half2_rn(gelu_exact(acc[tt][j][2]),
                                        gelu_exact(acc[tt][j][3]));
            } else {
                if (c0 < 38) {
                    dout[(size_t)r0 * 38 + c0]       = acc[tt][j][0];
                    dout[(size_t)(r0 + 8) * 38 + c0] = acc[tt][j][2];
                }
                if (c0 + 1 < 38) {
                    dout[(size_t)r0 * 38 + c0 + 1]       = acc[tt][j][1];
                    dout[(size_t)(r0 + 8) * 38 + c0 + 1] = acc[tt][j][3];
                }
            }
        }
        if (MODE == 0) {
            // zero logical cols 40..47 = permuted chunk-2 positions 4t+2,4t+3
            const __half2 z = __floats2half2_rn(0.f, 0.f);
            const int pz = 32 + 4 * t + 2;
            *(__half2*)&g_h[(size_t)r0 * 48 + pz]       = z;
            *(__half2*)&g_h[(size_t)(r0 + 8) * 48 + pz] = z;
        }
    }
}

// ------------------------------ launch ------------------------------------

extern "C" void kernel_launch(void* const* d_in, const int* in_sizes, int n_in,
                              void* d_out, int out_size) {
    const float* F   = (const float*)d_in[0];   // [400000, 64]
    const int*   nbr = (const int*)d_in[1];     // [27, 400000]
    const float* W1  = (const float*)d_in[2];   // [27, 64, 38]
    const float* W2  = (const float*)d_in[3];   // [27, 38, 38]
    float* out = (float*)d_out;                 // [400000, 38]

    prep_feat<<<((NPTS + 1) * 64 + 255) / 256, 256>>>(F);
    prep_w1f<<<(NOFF * 5 * 4 * 32 + 255) / 256, 256>>>(W1);
    prep_w2f<<<(NOFF * 5 * 3 * 32 + 255) / 256, 256>>>(W2);

    conv_r<64, 0><<<NPTS / 128, 128>>>(nbr, nullptr);   // L1 + GELU -> g_h
    conv_r<48, 1><<<NPTS / 128, 128>>>(nbr, out);       // L2 -> d_out
}